// round 12
// baseline (speedup 1.0000x reference)
#include <cuda_runtime.h>
#include <cuda_bf16.h>
#include <cstdint>
#include <cfloat>

#define BS   16
#define QN   1024
#define CN   92
#define TN   128

#define SCALE_D 36028797018963968.0   // 2^55
#define LL_INF  0x3FFFFFFFFFFFFFFFLL
#define ARR_CAP 512

// Transposed int64 fixed-point cost CtI[b][t][q] (exact monotone image of fp32).
__device__ long long g_CtI[BS * TN * QN];
// Per-(b,t) INVERTED packed row-min key (atomicMax of ~(fkey<<11|q)).
__device__ unsigned long long g_rowkeyInv[BS * TN];   // zero-init

__device__ __forceinline__ unsigned int fkey(float x) {
    unsigned int u = __float_as_uint(x);
    return (u & 0x80000000u) ? ~u : (u ^ 0x80000000u);
}
__device__ __forceinline__ float fkey_inv(unsigned int k) {
    unsigned int u = (k & 0x80000000u) ? (k ^ 0x80000000u) : ~k;
    return __uint_as_float(u);
}
__device__ __forceinline__ long long cvtll(float val) {
    return (long long)((double)val * SCALE_D);
}
__device__ __forceinline__ unsigned long long llkey(long long w, int j) {
    return ((((unsigned long long)w) ^ 0x8000000000000000ULL) & ~2047ULL)
           | (unsigned long long)j;
}

// ---------------------------------------------------------------------------
// Fused cost + transpose(int64) + row-min kernel. 32 warps = 32 queries/block.
// ---------------------------------------------------------------------------
__global__ void __launch_bounds__(1024)
cost_kernel(const float* __restrict__ logits,
            const float* __restrict__ points,
            const int*   __restrict__ lab32,
            const float* __restrict__ tpoints,
            float* __restrict__ outC)
{
    const int warp = threadIdx.x >> 5, lane = threadIdx.x & 31;
    const int b  = blockIdx.x >> 5;
    const int q0 = (blockIdx.x & 31) << 5;
    const int q  = q0 + warp;
    const int bq = (b << 10) + q;

    __shared__ float tile[TN][33];
    __shared__ float sprob[32][96];
    __shared__ int   slbl[TN];
    __shared__ float stx[TN], sty[TN];
    __shared__ int   s_lbl64;

    if (threadIdx.x == 0) s_lbl64 = 1;
    __syncthreads();
    if (threadIdx.x < TN) {
        if (lab32[2 * threadIdx.x + 1] != 0) s_lbl64 = 0;
    }
    __syncthreads();
    const int lbl64 = s_lbl64;

    if (threadIdx.x < TN) {
        const int lidx = b * TN + threadIdx.x;
        slbl[threadIdx.x] = lbl64 ? lab32[2 * lidx] : lab32[lidx];
        stx[threadIdx.x]  = tpoints[lidx * 2];
        sty[threadIdx.x]  = tpoints[lidx * 2 + 1];
    }

    const float* lg = logits + (size_t)bq * CN;
    const float a  = lg[lane];
    const float bb = lg[lane + 32];
    const float c  = (lane < 28) ? lg[lane + 64] : -FLT_MAX;

    float mx = fmaxf(a, fmaxf(bb, c));
    #pragma unroll
    for (int o = 16; o > 0; o >>= 1) mx = fmaxf(mx, __shfl_xor_sync(0xffffffffu, mx, o));

    const float ea = expf(a - mx);
    const float eb = expf(bb - mx);
    const float ec = (lane < 28) ? expf(c - mx) : 0.f;
    float e = ea + eb + ec;
    #pragma unroll
    for (int o = 16; o > 0; o >>= 1) e += __shfl_xor_sync(0xffffffffu, e, o);
    const float inv = 1.f / e;

    sprob[warp][lane]      = ea * inv;
    sprob[warp][lane + 32] = eb * inv;
    if (lane < 28) sprob[warp][lane + 64] = ec * inv;

    const float px = __ldg(points + bq * 2);
    const float py = __ldg(points + bq * 2 + 1);
    __syncthreads();

    #pragma unroll
    for (int c2 = 0; c2 < 4; c2++) {
        const int t = c2 * 32 + lane;
        const float cost = fabsf(px - stx[t]) + fabsf(py - sty[t])
                         - sprob[warp][slbl[t]];
        outC[(size_t)bq * TN + t] = cost;
        tile[t][warp] = cost;
    }
    __syncthreads();

    #pragma unroll
    for (int p = 0; p < 4; p++) {
        const int t = p * 32 + warp;
        const float val = tile[t][lane];
        g_CtI[((size_t)b * TN + t) * QN + q0 + lane] = cvtll(val);

        const unsigned int fk = fkey(val);
        const unsigned int mh = __reduce_min_sync(0xffffffffu, fk);
        const unsigned int win = __ffs(__ballot_sync(0xffffffffu, fk == mh)) - 1;
        if (lane == win) {
            const unsigned long long key =
                ((unsigned long long)mh << 11) | (unsigned long long)(q0 + lane);
            atomicMax(&g_rowkeyInv[b * TN + t], ~key);
        }
    }
}

// block argmin helper: warp REDUX (hi,lo) + lane0 atomicMin into slot
#define BLOCK_ARGMIN(KEY, SLOT)                                                 \
    {                                                                           \
        const unsigned int hi_ = (unsigned int)((KEY) >> 32);                   \
        const unsigned int mh_ = __reduce_min_sync(0xffffffffu, hi_);           \
        const unsigned int lo_ = (hi_ == mh_) ? (unsigned int)(KEY) : 0xffffffffu; \
        const unsigned int ml_ = __reduce_min_sync(0xffffffffu, lo_);           \
        if (lane == 0)                                                          \
            atomicMin(&s_key[SLOT],                                             \
                      ((unsigned long long)mh_ << 32) | (unsigned long long)ml_); \
    }

// ---------------------------------------------------------------------------
// Exact int64 JV: greedy row-min init -> ARR (augmenting row reduction,
// double-buffered value mirror) -> consistency sweep -> exact Dijkstra
// augmentation for leftovers. 1024 threads, 1 column/thread.
// ---------------------------------------------------------------------------
__global__ void __launch_bounds__(1024, 1)
lsa_kernel(float* __restrict__ outRow, float* __restrict__ outCol)
{
    const int b = blockIdx.x, tid = threadIdx.x;
    const int lane = tid & 31, warp = tid >> 5;

    __shared__ long long u_[TN];
    __shared__ long long SPa[2][QN];     // double-buffered value mirror
    __shared__ int    path_[QN];
    __shared__ int    row4col_[QN];
    __shared__ int    col4row_[TN];
    __shared__ int    list_[TN];
    __shared__ int    cnt_[4];
    __shared__ int    s_nfree, s_nexti, s_head;
    __shared__ unsigned long long s_key[3];

    const long long* C = g_CtI + (size_t)b * TN * QN;

    row4col_[tid] = -1;
    if (tid == 0) { s_key[0] = ~0ULL; s_key[1] = ~0ULL; s_key[2] = ~0ULL; }
    __syncthreads();

    // ---- greedy: duals + assignment from precomputed row-min keys ----
    if (tid < TN) {
        const unsigned long long key = ~g_rowkeyInv[b * TN + tid];
        const int js = (int)(key & 2047ULL);
        u_[tid] = cvtll(fkey_inv((unsigned int)(key >> 11)));
        const int old = atomicCAS(&row4col_[js], -1, tid);
        col4row_[tid] = (old == -1) ? js : -1;
    }
    __syncthreads();

    // ---- list of unassigned rows ----
    unsigned int bal = 0;
    if (tid < TN) {
        bal = __ballot_sync(0xffffffffu, col4row_[tid] < 0);
        if (lane == 0) cnt_[warp] = __popc(bal);
    }
    __syncthreads();
    if (tid < TN && col4row_[tid] < 0) {
        int base = 0;
        #pragma unroll
        for (int w = 0; w < 4; w++) if (w < warp) base += cnt_[w];
        list_[base + __popc(bal & ((1u << lane) - 1u))] = tid;
    }
    if (tid == 0) {
        s_nfree = cnt_[0] + cnt_[1] + cnt_[2] + cnt_[3];
        s_head  = 1;
    }
    __syncthreads();                       // list_ fully published BEFORE any read
    const int nfree = s_nfree;
    int i = (nfree > 0) ? list_[0] : -1;   // uniform, race-free initial row

    long long v = 0;        // this thread's column dual
    int t = 0;              // phase counter (3-slot rotation)

    // ---- ARR: augmenting row reduction (min + 2nd-min per free row) ----
    for (int iter = 0; i >= 0 && iter < ARR_CAP; ++iter) {
        const int par = iter & 1;
        // phase A: argmin of w = c - v
        if (tid == 0) s_key[(t + 1) % 3] = ~0ULL;
        const long long w = __ldg(C + (size_t)i * QN + tid) - v;
        SPa[par][tid] = w;
        const unsigned long long key = llkey(w, tid);
        BLOCK_ARGMIN(key, t % 3);
        __syncthreads();

        const int j1 = (int)(s_key[t % 3] & 2047ULL);
        t++;
        if (tid == 0) {
            s_key[(t + 1) % 3] = ~0ULL;
            const int r = row4col_[j1];
            row4col_[j1] = i;
            col4row_[i]  = j1;
            s_nexti = (r >= 0) ? r
                     : ((s_head < nfree) ? list_[s_head++] : -1);
        }

        // phase B: second-min (mask j1)
        const unsigned long long key2 = (tid == j1) ? ~0ULL : key;
        BLOCK_ARGMIN(key2, t % 3);
        __syncthreads();

        const int j2 = (int)(s_key[t % 3] & 2047ULL);
        t++;
        const long long u_i = SPa[par][j2];      // exact 2nd-min (double-buffered)
        if (tid == j1) v += (w - u_i);           // v[j1] = c - u_i (<= old v)
        if (tid == 0) u_[i] = u_i;
        i = s_nexti;                             // written pre-BAR, read post-BAR
    }
    __syncthreads();

    // ---- consistency sweep: free rows whose claim was evicted/interrupted ----
    if (tid < TN) {
        const int jr = col4row_[tid];
        if (jr >= 0 && row4col_[jr] != tid) col4row_[tid] = -1;
    }
    __syncthreads();

    // ---- exact Dijkstra augmentation for any rows still free ----
    for (int curRow = 0; curRow < TN; ++curRow) {
        if (col4row_[curRow] >= 0) continue;

        long long SP = LL_INF;
        unsigned long long lkey = ~0ULL;
        bool used = false;
        int ii = curRow;
        long long minVal = 0;
        int jsink;

        while (true) {
            const long long c = __ldg(C + (size_t)ii * QN + tid);
            if (tid == 0) s_key[(t + 1) % 3] = ~0ULL;
            const long long hk = minVal - u_[ii] - v;

            if (!used) {
                const long long r = c + hk;
                if (r < SP) {
                    SP = r; path_[tid] = ii; SPa[0][tid] = r;
                    lkey = llkey(r, tid);
                }
            }
            BLOCK_ARGMIN(lkey, t % 3);
            __syncthreads();

            const int j1 = (int)(s_key[t % 3] & 2047ULL);
            const int nr = row4col_[j1];
            minVal = SPa[0][j1];                 // safe: j1 marked used, never rewritten
            if (tid == j1) { used = true; lkey = ~0ULL; }
            t++;
            if (nr < 0) { jsink = j1; break; }
            ii = nr;
        }

        if (used) {
            const long long d = minVal - SP;
            v -= d;
            const int rj = row4col_[tid];
            if (rj >= 0) u_[rj] += d;
        }
        if (tid == 0) u_[curRow] += minVal;
        __syncthreads();

        if (tid == 0) {
            int j = jsink;
            while (true) {
                const int pi = path_[j];
                row4col_[j] = pi;
                const int tmp = col4row_[pi];
                col4row_[pi] = j;
                if (pi == curRow) break;
                j = tmp;
            }
        }
        __syncthreads();
    }

    // emit sorted by assigned query index
    if (tid < TN) {
        const int a = col4row_[tid];
        int r = 0;
        #pragma unroll 8
        for (int s = 0; s < TN; ++s) r += (col4row_[s] < a);
        outRow[b * TN + r] = (float)a;
        outCol[b * TN + r] = (float)tid;
    }
}

// ---------------------------------------------------------------------------
extern "C" void kernel_launch(void* const* d_in, const int* in_sizes, int n_in,
                              void* d_out, int out_size)
{
    const float* logits  = (const float*)d_in[0];
    const float* points  = (const float*)d_in[1];
    const int*   labels  = (const int*)  d_in[2];
    const float* tpoints = (const float*)d_in[3];

    float* out    = (float*)d_out;
    float* outC   = out;
    float* outRow = out + (size_t)BS * QN * TN;
    float* outCol = outRow + BS * TN;

    cost_kernel<<<BS * 32, 1024>>>(logits, points, labels, tpoints, outC);
    lsa_kernel<<<BS, 1024>>>(outRow, outCol);
}

// round 13
// speedup vs baseline: 1.3520x; 1.3520x over previous
#include <cuda_runtime.h>
#include <cuda_bf16.h>
#include <cstdint>
#include <cfloat>

#define BS   16
#define QN   1024
#define CN   92
#define TN   128

#define SCALE_D 36028797018963968.0   // 2^55
#define LL_INF  0x3FFFFFFFFFFFFFFFLL

// Transposed int64 fixed-point cost CtI[b][t][q] (exact monotone image of fp32).
__device__ long long g_CtI[BS * TN * QN];
// Per-(b,t) INVERTED packed row-min key (atomicMax of ~(fkey<<11|q)).
__device__ unsigned long long g_rowkeyInv[BS * TN];   // zero-init

__device__ __forceinline__ unsigned int fkey(float x) {
    unsigned int u = __float_as_uint(x);
    return (u & 0x80000000u) ? ~u : (u ^ 0x80000000u);
}
__device__ __forceinline__ float fkey_inv(unsigned int k) {
    unsigned int u = (k & 0x80000000u) ? (k ^ 0x80000000u) : ~k;
    return __uint_as_float(u);
}
__device__ __forceinline__ long long cvtll(float val) {
    return (long long)((double)val * SCALE_D);
}
__device__ __forceinline__ unsigned long long llkey(long long w, int j) {
    return ((((unsigned long long)w) ^ 0x8000000000000000ULL) & ~2047ULL)
           | (unsigned long long)j;
}

// ---------------------------------------------------------------------------
// Fused cost + transpose(int64) + row-min kernel. 32 warps = 32 queries/block.
// ---------------------------------------------------------------------------
__global__ void __launch_bounds__(1024)
cost_kernel(const float* __restrict__ logits,
            const float* __restrict__ points,
            const int*   __restrict__ lab32,
            const float* __restrict__ tpoints,
            float* __restrict__ outC)
{
    const int warp = threadIdx.x >> 5, lane = threadIdx.x & 31;
    const int b  = blockIdx.x >> 5;
    const int q0 = (blockIdx.x & 31) << 5;
    const int q  = q0 + warp;
    const int bq = (b << 10) + q;

    __shared__ float tile[TN][33];
    __shared__ float sprob[32][96];
    __shared__ int   slbl[TN];
    __shared__ float stx[TN], sty[TN];
    __shared__ int   s_lbl64;

    if (threadIdx.x == 0) s_lbl64 = 1;
    __syncthreads();
    if (threadIdx.x < TN) {
        if (lab32[2 * threadIdx.x + 1] != 0) s_lbl64 = 0;
    }
    __syncthreads();
    const int lbl64 = s_lbl64;

    if (threadIdx.x < TN) {
        const int lidx = b * TN + threadIdx.x;
        slbl[threadIdx.x] = lbl64 ? lab32[2 * lidx] : lab32[lidx];
        stx[threadIdx.x]  = tpoints[lidx * 2];
        sty[threadIdx.x]  = tpoints[lidx * 2 + 1];
    }

    const float* lg = logits + (size_t)bq * CN;
    const float a  = lg[lane];
    const float bb = lg[lane + 32];
    const float c  = (lane < 28) ? lg[lane + 64] : -FLT_MAX;

    float mx = fmaxf(a, fmaxf(bb, c));
    #pragma unroll
    for (int o = 16; o > 0; o >>= 1) mx = fmaxf(mx, __shfl_xor_sync(0xffffffffu, mx, o));

    const float ea = expf(a - mx);
    const float eb = expf(bb - mx);
    const float ec = (lane < 28) ? expf(c - mx) : 0.f;
    float e = ea + eb + ec;
    #pragma unroll
    for (int o = 16; o > 0; o >>= 1) e += __shfl_xor_sync(0xffffffffu, e, o);
    const float inv = 1.f / e;

    sprob[warp][lane]      = ea * inv;
    sprob[warp][lane + 32] = eb * inv;
    if (lane < 28) sprob[warp][lane + 64] = ec * inv;

    const float px = __ldg(points + bq * 2);
    const float py = __ldg(points + bq * 2 + 1);
    __syncthreads();

    #pragma unroll
    for (int c2 = 0; c2 < 4; c2++) {
        const int t = c2 * 32 + lane;
        const float cost = fabsf(px - stx[t]) + fabsf(py - sty[t])
                         - sprob[warp][slbl[t]];
        outC[(size_t)bq * TN + t] = cost;
        tile[t][warp] = cost;
    }
    __syncthreads();

    #pragma unroll
    for (int p = 0; p < 4; p++) {
        const int t = p * 32 + warp;
        const float val = tile[t][lane];
        g_CtI[((size_t)b * TN + t) * QN + q0 + lane] = cvtll(val);

        const unsigned int fk = fkey(val);
        const unsigned int mh = __reduce_min_sync(0xffffffffu, fk);
        const unsigned int win = __ffs(__ballot_sync(0xffffffffu, fk == mh)) - 1;
        if (lane == win) {
            const unsigned long long key =
                ((unsigned long long)mh << 11) | (unsigned long long)(q0 + lane);
            atomicMax(&g_rowkeyInv[b * TN + t], ~key);
        }
    }
}

// block argmin helper: warp REDUX (hi,lo) + lane0 atomicMin into slot
#define BLOCK_ARGMIN(KEY, SLOT)                                                 \
    {                                                                           \
        const unsigned int hi_ = (unsigned int)((KEY) >> 32);                   \
        const unsigned int mh_ = __reduce_min_sync(0xffffffffu, hi_);           \
        const unsigned int lo_ = (hi_ == mh_) ? (unsigned int)(KEY) : 0xffffffffu; \
        const unsigned int ml_ = __reduce_min_sync(0xffffffffu, lo_);           \
        if (lane == 0)                                                          \
            atomicMin(&s_key[SLOT],                                             \
                      ((unsigned long long)mh_ << 32) | (unsigned long long)ml_); \
    }

// ---------------------------------------------------------------------------
// Exact int64 JV (R9 structure): greedy row-min init -> exact Dijkstra
// augmentation for contested rows. 512 threads, TWO columns per thread
// (halves the warp count -> shallower same-address atomic chain + cheaper BAR).
// ---------------------------------------------------------------------------
__global__ void __launch_bounds__(512, 1)
lsa_kernel(float* __restrict__ outRow, float* __restrict__ outCol)
{
    const int b = blockIdx.x, tid = threadIdx.x;
    const int lane = tid & 31, warp = tid >> 5;

    __shared__ long long u_[TN];
    __shared__ long long SPsh[QN];
    __shared__ int    path_[QN];
    __shared__ int    row4col_[QN];
    __shared__ int    col4row_[TN];
    __shared__ int    list_[TN];
    __shared__ int    cnt_[4];
    __shared__ int    s_nfree;
    __shared__ unsigned long long s_key[3];

    const long long* C = g_CtI + (size_t)b * TN * QN;

    row4col_[tid * 2]     = -1;
    row4col_[tid * 2 + 1] = -1;
    if (tid == 0) { s_key[0] = ~0ULL; s_key[1] = ~0ULL; s_key[2] = ~0ULL; }
    __syncthreads();

    // ---- greedy: duals + assignment from precomputed row-min keys ----
    if (tid < TN) {
        const unsigned long long key = ~g_rowkeyInv[b * TN + tid];
        const int js = (int)(key & 2047ULL);
        u_[tid] = cvtll(fkey_inv((unsigned int)(key >> 11)));
        const int old = atomicCAS(&row4col_[js], -1, tid);
        col4row_[tid] = (old == -1) ? js : -1;
    }
    __syncthreads();

    // ---- list of unassigned rows ----
    unsigned int bal = 0;
    if (tid < TN) {
        bal = __ballot_sync(0xffffffffu, col4row_[tid] < 0);
        if (lane == 0) cnt_[warp] = __popc(bal);
    }
    __syncthreads();
    if (tid < TN && col4row_[tid] < 0) {
        int base = 0;
        #pragma unroll
        for (int w = 0; w < 4; w++) if (w < warp) base += cnt_[w];
        list_[base + __popc(bal & ((1u << lane) - 1u))] = tid;
    }
    if (tid == 0) s_nfree = cnt_[0] + cnt_[1] + cnt_[2] + cnt_[3];
    __syncthreads();
    const int nfree = s_nfree;

    long long v[2] = {0, 0};     // this thread's two column duals
    int t = 0;                   // step counter (3-slot rotation)

    for (int li = 0; li < nfree; ++li) {
        const int curRow = list_[li];

        long long SP[2] = {LL_INF, LL_INF};
        unsigned long long ckey[2] = {~0ULL, ~0ULL};  // cached packed keys
        int usedm = 0;
        int ii = curRow;
        long long minVal = 0;
        int jsink;

        while (true) {
            const long long c0 = __ldg(C + (size_t)ii * QN + tid * 2);
            const long long c1 = __ldg(C + (size_t)ii * QN + tid * 2 + 1);
            if (tid == 0) s_key[(t + 1) % 3] = ~0ULL;
            const long long base = minVal - u_[ii];

            if (!(usedm & 1)) {
                const long long r = c0 + base - v[0];
                if (r < SP[0]) {
                    SP[0] = r; path_[tid * 2] = ii; SPsh[tid * 2] = r;
                    ckey[0] = llkey(r, tid * 2);
                }
            }
            if (!(usedm & 2)) {
                const long long r = c1 + base - v[1];
                if (r < SP[1]) {
                    SP[1] = r; path_[tid * 2 + 1] = ii; SPsh[tid * 2 + 1] = r;
                    ckey[1] = llkey(r, tid * 2 + 1);
                }
            }
            const unsigned long long lkey = (ckey[0] < ckey[1]) ? ckey[0] : ckey[1];
            BLOCK_ARGMIN(lkey, t % 3);
            __syncthreads();                       // the ONLY per-step barrier

            const int j1 = (int)(s_key[t % 3] & 2047ULL);
            const int nr = row4col_[j1];
            minVal = SPsh[j1];                     // exact int64
            const int kown = j1 - tid * 2;
            if (kown == 0 || kown == 1) { usedm |= (1 << kown); ckey[kown] = ~0ULL; }
            t++;
            if (nr < 0) { jsink = j1; break; }
            ii = nr;
        }

        // dual update once per augmentation (reads row4col_ BEFORE augment)
        #pragma unroll
        for (int k = 0; k < 2; k++) {
            if ((usedm >> k) & 1) {
                const long long d = minVal - SP[k];
                v[k] -= d;
                const int rj = row4col_[tid * 2 + k];
                if (rj >= 0) u_[rj] += d;          // assigned rows distinct
            }
        }
        if (tid == 0) u_[curRow] += minVal;
        __syncthreads();

        if (tid == 0) {                            // augment
            int j = jsink;
            while (true) {
                const int pi = path_[j];
                row4col_[j] = pi;
                const int tmp = col4row_[pi];
                col4row_[pi] = j;
                if (pi == curRow) break;
                j = tmp;
            }
        }
        __syncthreads();
    }

    // emit sorted by assigned query index
    if (tid < TN) {
        const int a = col4row_[tid];
        int r = 0;
        #pragma unroll 8
        for (int s = 0; s < TN; ++s) r += (col4row_[s] < a);
        outRow[b * TN + r] = (float)a;
        outCol[b * TN + r] = (float)tid;
    }
}

// ---------------------------------------------------------------------------
extern "C" void kernel_launch(void* const* d_in, const int* in_sizes, int n_in,
                              void* d_out, int out_size)
{
    const float* logits  = (const float*)d_in[0];
    const float* points  = (const float*)d_in[1];
    const int*   labels  = (const int*)  d_in[2];
    const float* tpoints = (const float*)d_in[3];

    float* out    = (float*)d_out;
    float* outC   = out;
    float* outRow = out + (size_t)BS * QN * TN;
    float* outCol = outRow + BS * TN;

    cost_kernel<<<BS * 32, 1024>>>(logits, points, labels, tpoints, outC);
    lsa_kernel<<<BS, 512>>>(outRow, outCol);
}

// round 15
// speedup vs baseline: 1.4152x; 1.0468x over previous
#include <cuda_runtime.h>
#include <cuda_bf16.h>
#include <cstdint>
#include <cfloat>

#define BS   16
#define QN   1024
#define CN   92
#define TN   128

#define SCALE_D 536870912.0           // 2^29 (cost in (-1,2) -> fits int32)
#define LL_INF  0x3FFFFFFFFFFFFFFFLL

// Transposed int32 fixed-point cost CtI[b][t][q] (exact monotone image of fp32).
__device__ int g_CtI32[BS * TN * QN];
// Per-(b,t) INVERTED packed row-min key (atomicMax of ~(fkey<<11|q)); zero-init,
// idempotent across graph replays.
__device__ unsigned long long g_rowkeyInv[BS * TN];

__device__ __forceinline__ unsigned int fkey(float x) {
    unsigned int u = __float_as_uint(x);
    return (u & 0x80000000u) ? ~u : (u ^ 0x80000000u);
}
__device__ __forceinline__ float fkey_inv(unsigned int k) {
    unsigned int u = (k & 0x80000000u) ? (k ^ 0x80000000u) : ~k;
    return __uint_as_float(u);
}
// fp32 -> exact int fixed point (monotone; identical fn used for matrix and duals)
__device__ __forceinline__ long long cvtll(float val) {
    return (long long)((double)val * SCALE_D);
}

// ---------------------------------------------------------------------------
// Fused cost + transpose(int32) + row-min kernel. 32 warps = 32 queries/block.
// ---------------------------------------------------------------------------
__global__ void __launch_bounds__(1024)
cost_kernel(const float* __restrict__ logits,
            const float* __restrict__ points,
            const int*   __restrict__ lab32,
            const float* __restrict__ tpoints,
            float* __restrict__ outC)
{
    const int warp = threadIdx.x >> 5, lane = threadIdx.x & 31;
    const int b  = blockIdx.x >> 5;
    const int q0 = (blockIdx.x & 31) << 5;
    const int q  = q0 + warp;
    const int bq = (b << 10) + q;

    __shared__ float tile[TN][33];
    __shared__ float sprob[32][96];
    __shared__ int   slbl[TN];
    __shared__ float stx[TN], sty[TN];
    __shared__ int   s_lbl64;

    if (threadIdx.x == 0) s_lbl64 = 1;
    __syncthreads();
    if (threadIdx.x < TN) {
        if (lab32[2 * threadIdx.x + 1] != 0) s_lbl64 = 0;
    }
    __syncthreads();
    const int lbl64 = s_lbl64;

    if (threadIdx.x < TN) {
        const int lidx = b * TN + threadIdx.x;
        slbl[threadIdx.x] = lbl64 ? lab32[2 * lidx] : lab32[lidx];
        stx[threadIdx.x]  = tpoints[lidx * 2];
        sty[threadIdx.x]  = tpoints[lidx * 2 + 1];
    }

    const float* lg = logits + (size_t)bq * CN;
    const float a  = lg[lane];
    const float bb = lg[lane + 32];
    const float c  = (lane < 28) ? lg[lane + 64] : -FLT_MAX;

    float mx = fmaxf(a, fmaxf(bb, c));
    #pragma unroll
    for (int o = 16; o > 0; o >>= 1) mx = fmaxf(mx, __shfl_xor_sync(0xffffffffu, mx, o));

    const float ea = expf(a - mx);
    const float eb = expf(bb - mx);
    const float ec = (lane < 28) ? expf(c - mx) : 0.f;
    float e = ea + eb + ec;
    #pragma unroll
    for (int o = 16; o > 0; o >>= 1) e += __shfl_xor_sync(0xffffffffu, e, o);
    const float inv = 1.f / e;

    sprob[warp][lane]      = ea * inv;
    sprob[warp][lane + 32] = eb * inv;
    if (lane < 28) sprob[warp][lane + 64] = ec * inv;

    const float px = __ldg(points + bq * 2);
    const float py = __ldg(points + bq * 2 + 1);
    __syncthreads();   // publish slbl/stx/sty to ALL warps

    #pragma unroll
    for (int c2 = 0; c2 < 4; c2++) {
        const int t = c2 * 32 + lane;
        const float cost = fabsf(px - stx[t]) + fabsf(py - sty[t])
                         - sprob[warp][slbl[t]];
        outC[(size_t)bq * TN + t] = cost;
        tile[t][warp] = cost;
    }
    __syncthreads();

    // transposed int32 write + row-min (REDUX + one atomicMax per row segment)
    #pragma unroll
    for (int p = 0; p < 4; p++) {
        const int t = p * 32 + warp;
        const float val = tile[t][lane];
        g_CtI32[((size_t)b * TN + t) * QN + q0 + lane] = (int)cvtll(val);

        const unsigned int fk = fkey(val);
        const unsigned int mh = __reduce_min_sync(0xffffffffu, fk);
        const unsigned int win = __ffs(__ballot_sync(0xffffffffu, fk == mh)) - 1;
        if (lane == win) {
            const unsigned long long key =
                ((unsigned long long)mh << 11) | (unsigned long long)(q0 + lane);
            atomicMax(&g_rowkeyInv[b * TN + t], ~key);
        }
    }
}

// block argmin helper: warp REDUX (hi,lo) + lane0 atomicMin into slot
#define BLOCK_ARGMIN(KEY, SLOT)                                                 \
    {                                                                           \
        const unsigned int hi_ = (unsigned int)((KEY) >> 32);                   \
        const unsigned int mh_ = __reduce_min_sync(0xffffffffu, hi_);           \
        const unsigned int lo_ = (hi_ == mh_) ? (unsigned int)(KEY) : 0xffffffffu; \
        const unsigned int ml_ = __reduce_min_sync(0xffffffffu, lo_);           \
        if (lane == 0)                                                          \
            atomicMin(&s_key[SLOT],                                             \
                      ((unsigned long long)mh_ << 32) | (unsigned long long)ml_); \
    }

// build a step key: SP value (exact) << 19 | col << 8 | owner(8b, 255=free)
__device__ __forceinline__ unsigned long long stepkey(long long sp, int col, int nr) {
    return (((unsigned long long)sp) << 19)
         | ((unsigned long long)col << 8)
         | (unsigned long long)(nr & 255);
}

// ---------------------------------------------------------------------------
// Exact int JV: greedy row-min init -> exact Dijkstra augmentation.
// 512 threads, 2 columns/thread. The argmin key carries value+col+owner, so
// the post-barrier critical chain is ONE LDS (s_key) -> address -> LDG.
// ---------------------------------------------------------------------------
__global__ void __launch_bounds__(512, 1)
lsa_kernel(float* __restrict__ outRow, float* __restrict__ outCol)
{
    const int b = blockIdx.x, tid = threadIdx.x;
    const int lane = tid & 31, warp = tid >> 5;

    __shared__ long long u_[TN];
    __shared__ int    path_[QN];
    __shared__ int    row4col_[QN];
    __shared__ int    col4row_[TN];
    __shared__ int    list_[TN];
    __shared__ int    cnt_[4];
    __shared__ int    s_nfree;
    __shared__ unsigned long long s_key[3];

    const int* C = g_CtI32 + (size_t)b * TN * QN;
    const int j0c = tid * 2, j1c = tid * 2 + 1;

    row4col_[j0c] = -1;
    row4col_[j1c] = -1;
    if (tid == 0) { s_key[0] = ~0ULL; s_key[1] = ~0ULL; s_key[2] = ~0ULL; }
    __syncthreads();

    // ---- greedy: duals + assignment from precomputed row-min keys ----
    if (tid < TN) {
        const unsigned long long key = ~g_rowkeyInv[b * TN + tid];
        const int js = (int)(key & 2047ULL);
        u_[tid] = cvtll(fkey_inv((unsigned int)(key >> 11)));
        const int old = atomicCAS(&row4col_[js], -1, tid);
        col4row_[tid] = (old == -1) ? js : -1;
    }
    __syncthreads();

    // ---- list of unassigned rows ----
    unsigned int bal = 0;
    if (tid < TN) {
        bal = __ballot_sync(0xffffffffu, col4row_[tid] < 0);
        if (lane == 0) cnt_[warp] = __popc(bal);
    }
    __syncthreads();
    if (tid < TN && col4row_[tid] < 0) {
        int base = 0;
        #pragma unroll
        for (int w = 0; w < 4; w++) if (w < warp) base += cnt_[w];
        list_[base + __popc(bal & ((1u << lane) - 1u))] = tid;
    }
    if (tid == 0) s_nfree = cnt_[0] + cnt_[1] + cnt_[2] + cnt_[3];
    __syncthreads();
    const int nfree = s_nfree;

    long long v0 = 0, v1 = 0;   // this thread's two column duals
    int t = 0;                  // step counter (3-slot rotation)

    for (int li = 0; li < nfree; ++li) {
        const int curRow = list_[li];
        // owners of my two columns — STATIC during this search
        const int nr0 = row4col_[j0c];
        const int nr1 = row4col_[j1c];

        long long SP0 = LL_INF, SP1 = LL_INF;
        unsigned long long k0 = ~0ULL, k1 = ~0ULL;
        int usedm = 0;
        int ii = curRow;
        long long minVal = 0;
        int jsink;

        while (true) {
            const int2 cc = __ldg((const int2*)(C + (size_t)ii * QN) + tid);
            if (tid == 0) s_key[(t + 1) % 3] = ~0ULL;
            const long long base = minVal - u_[ii];

            if (!(usedm & 1)) {
                const long long r = (long long)cc.x + base - v0;
                if (r < SP0) { SP0 = r; path_[j0c] = ii; k0 = stepkey(r, j0c, nr0); }
            }
            if (!(usedm & 2)) {
                const long long r = (long long)cc.y + base - v1;
                if (r < SP1) { SP1 = r; path_[j1c] = ii; k1 = stepkey(r, j1c, nr1); }
            }
            const unsigned long long lkey = (k0 < k1) ? k0 : k1;
            BLOCK_ARGMIN(lkey, t % 3);
            __syncthreads();                       // the ONLY per-step barrier

            const unsigned long long kk = s_key[t % 3];
            const int j1 = (int)((kk >> 8) & 2047ULL);
            const int nrw = (int)(kk & 255ULL);
            minVal = (long long)(kk >> 19);        // exact (value embedded)
            if (j1 == j0c)      { usedm |= 1; k0 = ~0ULL; }
            else if (j1 == j1c) { usedm |= 2; k1 = ~0ULL; }
            t++;
            if (nrw == 255) { jsink = j1; break; }
            ii = nrw;
        }

        // dual update once per augmentation (owners are the PRE-augment ones)
        if (usedm & 1) {
            const long long d = minVal - SP0;
            v0 -= d;
            if (nr0 >= 0) u_[nr0] += d;
        }
        if (usedm & 2) {
            const long long d = minVal - SP1;
            v1 -= d;
            if (nr1 >= 0) u_[nr1] += d;
        }
        if (tid == 0) u_[curRow] += minVal;
        __syncthreads();

        if (tid == 0) {                            // augment
            int j = jsink;
            while (true) {
                const int pi = path_[j];
                row4col_[j] = pi;
                const int tmp = col4row_[pi];
                col4row_[pi] = j;
                if (pi == curRow) break;
                j = tmp;
            }
        }
        __syncthreads();
    }

    // emit sorted by assigned query index
    if (tid < TN) {
        const int a = col4row_[tid];
        int r = 0;
        #pragma unroll 8
        for (int s = 0; s < TN; ++s) r += (col4row_[s] < a);
        outRow[b * TN + r] = (float)a;
        outCol[b * TN + r] = (float)tid;
    }
}

// ---------------------------------------------------------------------------
extern "C" void kernel_launch(void* const* d_in, const int* in_sizes, int n_in,
                              void* d_out, int out_size)
{
    const float* logits  = (const float*)d_in[0];
    const float* points  = (const float*)d_in[1];
    const int*   labels  = (const int*)  d_in[2];
    const float* tpoints = (const float*)d_in[3];

    float* out    = (float*)d_out;
    float* outC   = out;
    float* outRow = out + (size_t)BS * QN * TN;
    float* outCol = outRow + BS * TN;

    cost_kernel<<<BS * 32, 1024>>>(logits, points, labels, tpoints, outC);
    lsa_kernel<<<BS, 512>>>(outRow, outCol);
}